// round 14
// baseline (speedup 1.0000x reference)
#include <cuda_runtime.h>
#include <cuda_fp16.h>
#include <cstdint>
#include <mma.h>
using namespace nvcuda;

#define DIM   1024
#define SEQL  4096
#define NB    2
#define NH    16
#define DH    64
#define WIN   512
#define NSEQ  (NB*SEQL)   // 8192
#define GKH   32          // gemm k-slab (halves)
#define GLDH  40          // gemm smem leading dim (halves; 80B rows, conflict-free)
#define LDA   72          // attn smem leading dim (halves; 144B rows)
#define LDS2  68          // attn float score/staging leading dim

// Scratch (allocation-free rule: __device__ globals)
__device__ __half g_xh[NSEQ*DIM];
__device__ __half g_wh[4*DIM*DIM];
__device__ __half g_qh[NSEQ*DIM];
__device__ __half g_kh[NSEQ*DIM];
__device__ __half g_vh[NSEQ*DIM];
__device__ __half g_ah[NSEQ*DIM];

__device__ __forceinline__ void cp16(uint32_t dst, const void* src){
    asm volatile("cp.async.cg.shared.global [%0], [%1], 16;" :: "r"(dst), "l"(src));
}

// ---------------------------------------------------------------------------
// Fused fp32 -> fp16 conversion: blockIdx.y picks segment (x, Wq, Wk, Wv, Wo).
// ---------------------------------------------------------------------------
__global__ void f2h5_kernel(
    const float4* __restrict__ x,
    const float4* __restrict__ wq, const float4* __restrict__ wk,
    const float4* __restrict__ wv, const float4* __restrict__ wo,
    uint2* __restrict__ xh, uint2* __restrict__ wh)
{
    const int seg = blockIdx.y;
    const float4* src;
    uint2* dst;
    int n4;
    if (seg == 0){ src = x;  dst = xh;                      n4 = NSEQ*DIM/4; }
    else {
        src = (seg==1) ? wq : (seg==2) ? wk : (seg==3) ? wv : wo;
        dst = wh + (size_t)(seg-1)*(DIM*DIM/4);
        n4  = DIM*DIM/4;
    }
    for (int i = blockIdx.x*blockDim.x + threadIdx.x; i < n4; i += gridDim.x*blockDim.x){
        float4 v = src[i];
        __half2 h0 = __floats2half2_rn(v.x, v.y);
        __half2 h1 = __floats2half2_rn(v.z, v.w);
        uint2 o; o.x = *(uint32_t*)&h0; o.y = *(uint32_t*)&h1;
        dst[i] = o;
    }
}

// ---------------------------------------------------------------------------
// C[n,m] = sum_k A[n,k]*Wt[m,k] + bias[m].  fp16 in, fp32 acc.
// Block tile 256x128, 512 threads (16 warps 4x4, warp tile 64x32), m16n16k16.
// Same register-prefetch double-buffer skeleton as the measured R12 kernel;
// only the row-tile count scaled 2x (cuts aggregate A/W traffic 27%).
// blockIdx.z selects (W,bias,C) -> fused QKV. out_half: write fp16 else fp32.
// ---------------------------------------------------------------------------
#define ASLAB (256*GLDH)          // halves per A slab
#define STG_H ((256+128)*GLDH)    // halves per stage (A + B)

__global__ __launch_bounds__(512) void gemm3h_kernel(
    const __half* __restrict__ A,
    const __half* __restrict__ W0, const __half* __restrict__ W1, const __half* __restrict__ W2,
    const float* __restrict__ b0, const float* __restrict__ b1, const float* __restrict__ b2,
    void* __restrict__ C0, void* __restrict__ C1, void* __restrict__ C2,
    int out_half)
{
    const int z = blockIdx.z;
    const __half* __restrict__ Wt   = (z==0) ? W0 : (z==1) ? W1 : W2;
    const float*  __restrict__ bias = (z==0) ? b0 : (z==1) ? b1 : b2;
    void* Cv                        = (z==0) ? C0 : (z==1) ? C1 : C2;

    extern __shared__ __align__(128) __half sm[];   // 2 stages * STG_H halves

    const int n0 = blockIdx.y * 256;
    const int m0 = blockIdx.x * 128;
    const int t  = threadIdx.x;
    const int w  = t >> 5;
    const int wr = w >> 2;            // 0..3 : 64-row group
    const int wc = w & 3;             // 0..3 : 32-col group

    wmma::fragment<wmma::accumulator,16,16,16,float> acc[4][2];
    #pragma unroll
    for (int i=0;i<4;i++)
        #pragma unroll
        for (int j=0;j<2;j++) wmma::fill_fragment(acc[i][j], 0.0f);

    uint4 ra[2], rb;                  // A: 256x32 halves (2/thr), B: 128x32 (1/thr)

    auto LOADR = [&](int ks){
        #pragma unroll
        for (int j=0;j<2;j++){
            int idx = t + j*512;      // 0..1023 uint4s
            int r  = idx >> 2;        // 0..255
            int c8 = (idx & 3) * 8;
            ra[j] = *(const uint4*)&A[(size_t)(n0 + r)*DIM + ks*GKH + c8];
        }
        {
            int r  = t >> 2;          // 0..127
            int c8 = (t & 3) * 8;
            rb = *(const uint4*)&Wt[(size_t)(m0 + r)*DIM + ks*GKH + c8];
        }
    };
    auto STORES = [&](int st){
        __half* sA = sm + st*STG_H;
        __half* sB = sA + ASLAB;
        #pragma unroll
        for (int j=0;j<2;j++){
            int idx = t + j*512;
            int r  = idx >> 2;
            int c8 = (idx & 3) * 8;
            *(uint4*)&sA[r*GLDH + c8] = ra[j];
        }
        {
            int r  = t >> 2;
            int c8 = (t & 3) * 8;
            *(uint4*)&sB[r*GLDH + c8] = rb;
        }
    };
    auto COMPUTE = [&](int st){
        const __half* sA = sm + st*STG_H;
        const __half* sB = sA + ASLAB;
        #pragma unroll
        for (int ks = 0; ks < 2; ks++){
            int kk = ks*16;
            wmma::fragment<wmma::matrix_a,16,16,16,__half,wmma::row_major> af[4];
            wmma::fragment<wmma::matrix_b,16,16,16,__half,wmma::col_major> bf[2];
            #pragma unroll
            for (int i=0;i<4;i++)
                wmma::load_matrix_sync(af[i], &sA[(wr*64 + i*16)*GLDH + kk], GLDH);
            #pragma unroll
            for (int j=0;j<2;j++)
                wmma::load_matrix_sync(bf[j], &sB[(wc*32 + j*16)*GLDH + kk], GLDH);
            #pragma unroll
            for (int i=0;i<4;i++)
                #pragma unroll
                for (int j=0;j<2;j++)
                    wmma::mma_sync(acc[i][j], af[i], bf[j], acc[i][j]);
        }
    };

    const int NS = DIM / GKH;         // 32 slabs
    LOADR(0); STORES(0);
    LOADR(1);
    __syncthreads();
    for (int ks = 0; ks < NS; ks++){
        if (ks + 1 < NS) STORES((ks+1)&1);
        if (ks + 2 < NS) LOADR(ks+2);
        COMPUTE(ks&1);
        __syncthreads();
    }

    // Epilogue: four 64-row passes via float smem staging, bias add.
    float* sC = (float*)sm;           // 64x132 floats = 33792B <= stage mem
    #pragma unroll
    for (int h = 0; h < 4; h++){
        if (wr == h){
            #pragma unroll
            for (int i=0;i<4;i++)
                #pragma unroll
                for (int j=0;j<2;j++)
                    wmma::store_matrix_sync(&sC[(i*16)*132 + wc*32 + j*16],
                                            acc[i][j], 132, wmma::mem_row_major);
        }
        __syncthreads();
        #pragma unroll
        for (int i=0;i<4;i++){
            int f  = t + i*512;       // 0..2047 float4s of 64x128
            int r  = f >> 5;
            int c4 = (f & 31) * 4;
            float4 vv = *(float4*)&sC[r*132 + c4];
            int m = m0 + c4;
            vv.x += bias[m]; vv.y += bias[m+1]; vv.z += bias[m+2]; vv.w += bias[m+3];
            if (out_half){
                __half2 h0 = __floats2half2_rn(vv.x, vv.y);
                __half2 h1 = __floats2half2_rn(vv.z, vv.w);
                uint2 o; o.x = *(uint32_t*)&h0; o.y = *(uint32_t*)&h1;
                *(uint2*)((__half*)Cv + (size_t)(n0 + h*64 + r)*DIM + m) = o;
            } else {
                *(float4*)((float*)Cv + (size_t)(n0 + h*64 + r)*DIM + m) = vv;
            }
        }
        __syncthreads();
    }
}

// ---------------------------------------------------------------------------
// Sliding-window attention, fp16 tiles / fp32 accumulate+softmax.
// Block = (b, chunk, head, 128-query tile), 512 threads (R12-measured skeleton).
// Change vs R12: per-warp-patch exp (warp-private S region) removes one CTA
// barrier per KV tile (3 -> 2).
// ---------------------------------------------------------------------------
__global__ __launch_bounds__(512,1) void attn_kernel(
    const __half* __restrict__ q, const __half* __restrict__ k,
    const __half* __restrict__ v, __half* __restrict__ o)
{
    extern __shared__ uint8_t smraw[];
    uintptr_t basep = ((uintptr_t)smraw + 127) & ~(uintptr_t)127;
    __half* sQ    = (__half*)basep;                        // 128*72 h
    __half* sKb[2] = { sQ + 128*LDA,          sQ + 128*LDA + 64*LDA };
    __half* sVb[2] = { sKb[1] + 64*LDA,       sKb[1] + 2*64*LDA };
    __half* sPh   = sVb[1] + 64*LDA;                       // 128*72 h
    float*  sS    = (float*)(sPh + 128*LDA);               // 128*68 f
    float*  sDen  = sS + 128*LDS2;                         // 128
    float*  sPart = sDen + 128;                            // 512

    const int bx = blockIdx.x;
    const int qt = bx & 3;
    const int h  = (bx >> 2) & 15;
    const int c  = (bx >> 6) & 7;
    const int b  = bx >> 9;

    const int t = threadIdx.x;
    const int w = t >> 5;
    const int lane = t & 31;
    const int qrow = w >> 1;              // 0..7
    const int cgrp = w & 1;               // 0..1

    const size_t qbase = ((size_t)(b*SEQL + c*WIN + qt*128))*DIM + h*DH;
    const int kstart = (c == 0) ? 0 : (c-1)*WIN;
    const int ntiles = (c == 0) ? 8 : 16;
    const __half* kg0 = k + ((size_t)(b*SEQL + kstart))*DIM + h*DH;
    const __half* vg0 = v + ((size_t)(b*SEQL + kstart))*DIM + h*DH;

    uint32_t sK_a[2] = { (uint32_t)__cvta_generic_to_shared(sKb[0]),
                         (uint32_t)__cvta_generic_to_shared(sKb[1]) };
    uint32_t sV_a[2] = { (uint32_t)__cvta_generic_to_shared(sVb[0]),
                         (uint32_t)__cvta_generic_to_shared(sVb[1]) };

    auto ISSUE = [&](int tile, int buf){
        const __half* kg = kg0 + (size_t)tile*64*DIM;
        const __half* vg = vg0 + (size_t)tile*64*DIM;
        int r  = t >> 3;
        int c8 = (t & 7) * 8;
        uint32_t off = (uint32_t)((r*LDA + c8)*2);
        cp16(sK_a[buf] + off, kg + (size_t)r*DIM + c8);
        cp16(sV_a[buf] + off, vg + (size_t)r*DIM + c8);
        asm volatile("cp.async.commit_group;");
    };

    ISSUE(0, 0);

    // Q tile (128x64 halves), scaled by 1/sqrt(dh)=0.125 (exact in fp16)
    {
        const __half2 sc = __float2half2_rn(0.125f);
        #pragma unroll
        for (int i=0;i<2;i++){
            int f = t + i*512;
            int r = f >> 3; int c8 = (f & 7)*8;
            uint4 u = *(const uint4*)&q[qbase + (size_t)r*DIM + c8];
            __half2* hp = (__half2*)&u;
            #pragma unroll
            for (int j=0;j<4;j++) hp[j] = __hmul2(hp[j], sc);
            *(uint4*)&sQ[r*LDA + c8] = u;
        }
    }
    if (t < 128) sDen[t] = 0.0f;

    wmma::fragment<wmma::accumulator,16,16,16,float> oacc[2];
    wmma::fill_fragment(oacc[0], 0.0f);
    wmma::fill_fragment(oacc[1], 0.0f);

    for (int tile = 0; tile < ntiles; tile++) {
        asm volatile("cp.async.wait_group 0;");
        __syncthreads();
        const int buf = tile & 1;
        if (tile + 1 < ntiles) ISSUE(tile+1, buf ^ 1);

        // S = (Q*scale) @ K^T   [128 x 64]
        wmma::fragment<wmma::accumulator,16,16,16,float> sacc[2];
        wmma::fill_fragment(sacc[0], 0.0f);
        wmma::fill_fragment(sacc[1], 0.0f);
        #pragma unroll
        for (int kk=0; kk<64; kk+=16){
            wmma::fragment<wmma::matrix_a,16,16,16,__half,wmma::row_major> af;
            wmma::load_matrix_sync(af, &sQ[qrow*16*LDA + kk], LDA);
            #pragma unroll
            for (int j=0;j<2;j++){
                wmma::fragment<wmma::matrix_b,16,16,16,__half,wmma::col_major> bf;
                wmma::load_matrix_sync(bf, &sKb[buf][(cgrp*32 + j*16)*LDA + kk], LDA);
                wmma::mma_sync(sacc[j], af, bf, sacc[j]);
            }
        }
        #pragma unroll
        for (int j=0;j<2;j++)
            wmma::store_matrix_sync(&sS[qrow*16*LDS2 + cgrp*32 + j*16], sacc[j],
                                    LDS2, wmma::mem_row_major);
        __syncwarp();

        // Per-warp patch exp: this warp exps exactly the 16x32 region it wrote.
        {
            int rloc    = lane & 15;          // row within patch
            int colhalf = lane >> 4;          // 0..1 : 16-col half of the patch
            int r = qrow*16 + rloc;
            const float* rowf = &sS[r*LDS2 + cgrp*32 + colhalf*16];
            __half hbuf[16];
            float s = 0.0f;
            #pragma unroll
            for (int j=0;j<16;j++){
                float p = __expf(rowf[j]);
                hbuf[j] = __float2half_rn(p);
                s += p;
            }
            *(uint4*)&sPh[r*LDA + cgrp*32 + colhalf*16]     = *(uint4*)&hbuf[0];
            *(uint4*)&sPh[r*LDA + cgrp*32 + colhalf*16 + 8] = *(uint4*)&hbuf[8];
            sPart[(cgrp*2 + colhalf)*128 + r] = s;
        }
        __syncthreads();
        if (t < 128)
            sDen[t] += sPart[t] + sPart[128+t] + sPart[256+t] + sPart[384+t];

        // O += P @ V   (P fp16, V fp16, acc fp32)
        #pragma unroll
        for (int kk=0; kk<64; kk+=16){
            wmma::fragment<wmma::matrix_a,16,16,16,__half,wmma::row_major> af;
            wmma::load_matrix_sync(af, &sPh[qrow*16*LDA + kk], LDA);
            #pragma unroll
            for (int j=0;j<2;j++){
                wmma::fragment<wmma::matrix_b,16,16,16,__half,wmma::row_major> bf;
                wmma::load_matrix_sync(bf, &sVb[buf][kk*LDA + cgrp*32 + j*16], LDA);
                wmma::mma_sync(oacc[j], af, bf, oacc[j]);
            }
        }
    }

    __syncthreads();
    #pragma unroll
    for (int j=0;j<2;j++)
        wmma::store_matrix_sync(&sS[qrow*16*LDS2 + cgrp*32 + j*16], oacc[j],
                                LDS2, wmma::mem_row_major);
    __syncthreads();
    #pragma unroll
    for (int i=0;i<4;i++){
        int f = t + i*512;                // 128 rows x 16 float4
        int r = f >> 4; int c4 = (f & 15)*4;
        float inv = 1.0f / sDen[r];
        float4 vo = *(float4*)&sS[r*LDS2 + c4];
        __half2 h0 = __floats2half2_rn(vo.x*inv, vo.y*inv);
        __half2 h1 = __floats2half2_rn(vo.z*inv, vo.w*inv);
        uint2 u; u.x = *(uint32_t*)&h0; u.y = *(uint32_t*)&h1;
        *(uint2*)&o[qbase + (size_t)r*DIM + c4] = u;
    }
}

// ---------------------------------------------------------------------------
extern "C" void kernel_launch(void* const* d_in, const int* in_sizes, int n_in,
                              void* d_out, int out_size)
{
    const float* x  = (const float*)d_in[0];
    const float* Wq = (const float*)d_in[1];
    const float* bq = (const float*)d_in[2];
    const float* Wk = (const float*)d_in[3];
    const float* bk = (const float*)d_in[4];
    const float* Wv = (const float*)d_in[5];
    const float* bv = (const float*)d_in[6];
    const float* Wo = (const float*)d_in[7];
    const float* bo = (const float*)d_in[8];
    float* out = (float*)d_out;

    __half *xh, *wh, *qh, *kh, *vh, *ah;
    cudaGetSymbolAddress((void**)&xh, g_xh);
    cudaGetSymbolAddress((void**)&wh, g_wh);
    cudaGetSymbolAddress((void**)&qh, g_qh);
    cudaGetSymbolAddress((void**)&kh, g_kh);
    cudaGetSymbolAddress((void**)&vh, g_vh);
    cudaGetSymbolAddress((void**)&ah, g_ah);

    const int gemm_smem = 2 * STG_H * 2;       // 2 stages * (256+128)*40 halves * 2B = 61440
    const int attn_smem =
        (128*LDA + 4*64*LDA + 128*LDA) * 2
      + (128*LDS2 + 128 + 512) * 4
      + 128;
    cudaFuncSetAttribute(gemm3h_kernel, cudaFuncAttributeMaxDynamicSharedMemorySize, gemm_smem);
    cudaFuncSetAttribute(attn_kernel,   cudaFuncAttributeMaxDynamicSharedMemorySize, attn_smem);

    // Single fused fp32->fp16 conversion launch (x + 4 weights).
    f2h5_kernel<<<dim3(128,5), 256>>>(
        (const float4*)x, (const float4*)Wq, (const float4*)Wk,
        (const float4*)Wv, (const float4*)Wo, (uint2*)xh, (uint2*)wh);

    // Fused QKV: grid.z = 3; fp16 outputs.
    dim3 gqkv(DIM/128, NSEQ/256, 3);
    gemm3h_kernel<<<gqkv, 512, gemm_smem>>>(
        xh, wh + 0*DIM*DIM, wh + 1*DIM*DIM, wh + 2*DIM*DIM,
        bq, bk, bv, qh, kh, vh, 1);

    attn_kernel<<<NB*8*NH*4, 512, attn_smem>>>(qh, kh, vh, ah);

    // Output projection: fp16 inputs, fp32 output with bias.
    dim3 gout(DIM/128, NSEQ/256, 1);
    gemm3h_kernel<<<gout, 512, gemm_smem>>>(
        ah, wh + 3*DIM*DIM, wh + 3*DIM*DIM, wh + 3*DIM*DIM,
        bo, bo, bo, out, out, out, 0);
}